// round 1
// baseline (speedup 1.0000x reference)
#include <cuda_runtime.h>
#include <cstdint>
#include <cfloat>
#include <math.h>

#define BB   2
#define NNN  2048
#define DIMM 1024
#define HHH  16
#define DHH  64
#define MMM  16
#define JJJ  2064   // M + N
#define ROTD 32

// d_out layout (floats): out | pre | post
#define OFF_OUT  0
#define OFF_PRE  (BB*NNN*DIMM)                       // 4194304
#define OFF_POST (OFF_PRE + BB*HHH*NNN*JJJ)         // 139460608

// ---- scratch (device globals; allocation-free rule) ----
__device__ float g_q  [BB*HHH*NNN*DHH];                 // (b,h,i,d)
__device__ float g_k  [BB*HHH*JJJ*DHH];                 // (b,h,j,d)  j=0..15 memory
__device__ float g_vT [BB*HHH*DHH*JJJ];                 // (b,h,d,j)
__device__ float g_attn2[(size_t)BB*HHH*NNN*JJJ];       // post-mixed attention
__device__ float g_oh [BB*NNN*HHH*DHH];                 // (b,i, h*64+d)

// ---------------- tf32 mma helpers ----------------
__device__ __forceinline__ uint32_t f2tf(float f) {
    uint32_t u; asm("cvt.rna.tf32.f32 %0, %1;" : "=r"(u) : "f"(f)); return u;
}
__device__ __forceinline__ void mma8(float c[4], const uint32_t a[4], const uint32_t b[2]) {
    asm volatile(
        "mma.sync.aligned.m16n8k8.row.col.f32.tf32.tf32.f32 "
        "{%0,%1,%2,%3},{%4,%5,%6,%7},{%8,%9},{%0,%1,%2,%3};"
        : "+f"(c[0]), "+f"(c[1]), "+f"(c[2]), "+f"(c[3])
        : "r"(a[0]), "r"(a[1]), "r"(a[2]), "r"(a[3]), "r"(b[0]), "r"(b[1]));
}

// Warp computes a 32x32 C tile from smem tiles As[64][S], Bs[64][S] (B stored as [n][k]).
template<int S>
__device__ __forceinline__ void warp_tile_mma(const float* As, const float* Bs,
                                              int mw, int nw, int kc, int lane,
                                              float acc[2][4][4]) {
    const int r = lane >> 2, q = lane & 3;
    for (int k0 = 0; k0 < kc; k0 += 8) {
        uint32_t a[2][4];
#pragma unroll
        for (int mt = 0; mt < 2; mt++) {
            const float* p = As + (mw + mt*16 + r) * S + k0 + q;
            a[mt][0] = f2tf(p[0]);
            a[mt][1] = f2tf(p[8*S]);
            a[mt][2] = f2tf(p[4]);
            a[mt][3] = f2tf(p[8*S + 4]);
        }
#pragma unroll
        for (int nt = 0; nt < 4; nt++) {
            const float* p = Bs + (nw + nt*8 + r) * S + k0 + q;
            uint32_t b[2];
            b[0] = f2tf(p[0]);
            b[1] = f2tf(p[4]);
#pragma unroll
            for (int mt = 0; mt < 2; mt++) mma8(acc[mt][nt], a[mt], b);
        }
    }
}

// ---------------- K0: broadcast memory K/V ----------------
__global__ void k_memfill(const float* __restrict__ mem_k, const float* __restrict__ mem_v) {
    int bh = blockIdx.x;            // b*16+h
    int h  = bh & 15;
    for (int idx = threadIdx.x; idx < MMM*DHH; idx += blockDim.x) {
        int j = idx >> 6, d = idx & 63;
        float kv = mem_k[(h*MMM + j)*DHH + d];
        float vv = mem_v[(h*MMM + j)*DHH + d];
        g_k [((size_t)bh*JJJ + j)*DHH + d] = kv;
        g_vT[((size_t)bh*DHH + d)*JJJ + j] = vv;
    }
}

// ---------------- K1: QKV projection + rotary ----------------
// grid (48, 64): x = n-tile (16 per matrix), y = m-tile. block 128.
__global__ void k_qkv(const float* __restrict__ x,
                      const float* __restrict__ Wq, const float* __restrict__ Wk,
                      const float* __restrict__ Wv, const float* __restrict__ rot) {
    __shared__ float As[64*36];
    __shared__ float Bs[64*36];
    const int tid = threadIdx.x, lane = tid & 31, w = tid >> 5;
    const int mbase = blockIdx.y * 64;
    const int ntile = blockIdx.x;
    const int which = ntile / 16;            // 0=q 1=k 2=v
    const float* W = (which == 0) ? Wq : (which == 1 ? Wk : Wv);
    const int nlocal = (ntile % 16) * 64;    // within the 1024-wide W
    const int h = ntile % 16;

    float acc[2][4][4];
#pragma unroll
    for (int a = 0; a < 2; a++)
#pragma unroll
        for (int b = 0; b < 4; b++)
#pragma unroll
            for (int c = 0; c < 4; c++) acc[a][b][c] = 0.f;

    for (int kc = 0; kc < 1024; kc += 32) {
#pragma unroll
        for (int t = 0; t < 4; t++) {
            int idx = tid + t*128;                 // float4 index, 512 total
            int row = idx >> 3, col4 = (idx & 7) * 4;
            float4 va = *(const float4*)&x[(size_t)(mbase + row)*1024 + kc + col4];
            *(float4*)&As[row*36 + col4] = va;
            float4 vb = *(const float4*)&W[(size_t)(nlocal + row)*1024 + kc + col4];
            *(float4*)&Bs[row*36 + col4] = vb;
        }
        __syncthreads();
        warp_tile_mma<36>(As, Bs, (w >> 1)*32, (w & 1)*32, 32, lane, acc);
        __syncthreads();
    }

    const int r = lane >> 2, q = lane & 3;
    const int mw = (w >> 1)*32, nw = (w & 1)*32;
    const bool lower = (nw == 0);

#pragma unroll
    for (int mt = 0; mt < 2; mt++) {
#pragma unroll
        for (int ci = 0; ci < 4; ci++) {
            int row = mbase + mw + mt*16 + r + ((ci & 2) ? 8 : 0);
            int b = row >> 11, i = row & 2047;
            if (which < 2 && lower) {
                // rotary: pair (d, d+16) lives in (nt, nt+2)
#pragma unroll
                for (int nt = 0; nt < 2; nt++) {
                    int d = nt*8 + 2*q + (ci & 1);          // 0..15
                    float lo = acc[mt][nt][ci];
                    float hi = acc[mt][nt + 2][ci];
                    float ang = rot[i*ROTD + d];            // rot repeats every 16
                    float cs = cosf(ang), sn = sinf(ang);
                    acc[mt][nt][ci]     = lo*cs - hi*sn;
                    acc[mt][nt + 2][ci] = hi*cs + lo*sn;
                }
            }
#pragma unroll
            for (int nt = 0; nt < 4; nt++) {
                int d = nw + nt*8 + 2*q + (ci & 1);
                float v = acc[mt][nt][ci];
                size_t bh = (size_t)(b*16 + h);
                if (which == 0)      g_q [(bh*NNN + i)*DHH + d] = v;
                else if (which == 1) g_k [(bh*JJJ + i + 16)*DHH + d] = v;
                else                 g_vT[(bh*DHH + d)*JJJ + (i + 16)] = v;
            }
        }
    }
}

// ---------------- K2: dots = scale * q @ k^T  -> pre ----------------
// grid (33, 32, 32): x=j-tile, y=i-tile, z=bh. block 128.
__global__ void k_dots(float* __restrict__ pre) {
    __shared__ float As[64*68];
    __shared__ float Bs[64*68];
    const int tid = threadIdx.x, lane = tid & 31, w = tid >> 5;
    const int bh = blockIdx.z;
    const int mbase = blockIdx.y * 64;
    const int jbase = blockIdx.x * 64;

    // load q tile (64x64) and k tile (64x64, guarded)
#pragma unroll
    for (int t = 0; t < 8; t++) {
        int idx = tid + t*128;                 // 1024 float4
        int row = idx >> 4, col4 = (idx & 15) * 4;
        float4 va = *(const float4*)&g_q[((size_t)bh*NNN + mbase + row)*DHH + col4];
        *(float4*)&As[row*68 + col4] = va;
        int j = jbase + row;
        float4 vb = (j < JJJ)
            ? *(const float4*)&g_k[((size_t)bh*JJJ + j)*DHH + col4]
            : make_float4(0.f, 0.f, 0.f, 0.f);
        *(float4*)&Bs[row*68 + col4] = vb;
    }
    __syncthreads();

    float acc[2][4][4];
#pragma unroll
    for (int a = 0; a < 2; a++)
#pragma unroll
        for (int b = 0; b < 4; b++)
#pragma unroll
            for (int c = 0; c < 4; c++) acc[a][b][c] = 0.f;

    warp_tile_mma<68>(As, Bs, (w >> 1)*32, (w & 1)*32, 64, lane, acc);

    const int r = lane >> 2, q = lane & 3;
    const int mw = (w >> 1)*32, nw = (w & 1)*32;
#pragma unroll
    for (int mt = 0; mt < 2; mt++)
#pragma unroll
        for (int ci = 0; ci < 4; ci++) {
            int row = mbase + mw + mt*16 + r + ((ci & 2) ? 8 : 0);
#pragma unroll
            for (int nt = 0; nt < 4; nt++) {
                int j = jbase + nw + nt*8 + 2*q + (ci & 1);
                if (j < JJJ)
                    pre[((size_t)bh*NNN + row)*JJJ + j] = acc[mt][nt][ci] * 0.125f;
            }
        }
}

// ---------------- K3: head-mix + mask + softmax + post-mix ----------------
// grid 4096 (b*2048+i), block 256, dyn smem ~134.8KB
__global__ void k_mixsoftmax(const float* __restrict__ pre,
                             float* __restrict__ post,
                             const float* __restrict__ preP,
                             const float* __restrict__ postP) {
    extern __shared__ float sm[];
    float* sPre = sm;                    // [16][2064]
    float* sP   = sm + 16*JJJ;           // 256
    float* sQ   = sP + 256;              // 256
    float* wbuf = sQ + 256;              // 128
    float* maxs = wbuf + 128;            // 16
    float* sums = maxs + 16;             // 16

    const int bx = blockIdx.x;
    const int b = bx >> 11, i = bx & 2047;
    const int tid = threadIdx.x, lane = tid & 31, wid = tid >> 5;

    for (int h = 0; h < 16; h++)
        for (int j = tid; j < JJJ; j += 256)
            sPre[h*JJJ + j] = pre[(((size_t)(b*16 + h))*NNN + i)*JJJ + j];
    if (tid < 256) { sP[tid] = preP[tid]; sQ[tid] = postP[tid]; }
    __syncthreads();

    float lmax[16];
#pragma unroll
    for (int k = 0; k < 16; k++) lmax[k] = -FLT_MAX;

    // mix (in-place per column) + local max over unmasked
    for (int j = tid; j < JJJ; j += 256) {
        bool masked = (j > i + 16);
        float dv[16];
#pragma unroll
        for (int h = 0; h < 16; h++) dv[h] = sPre[h*JJJ + j];
        float mix[16];
#pragma unroll
        for (int k = 0; k < 16; k++) {
            float s = 0.f;
#pragma unroll
            for (int h = 0; h < 16; h++) s += dv[h] * sP[h*16 + k];
            mix[k] = s;
        }
#pragma unroll
        for (int k = 0; k < 16; k++) sPre[k*JJJ + j] = mix[k];
        if (!masked) {
#pragma unroll
            for (int k = 0; k < 16; k++) lmax[k] = fmaxf(lmax[k], mix[k]);
        }
    }
    // reduce max
#pragma unroll
    for (int k = 0; k < 16; k++) {
        float v = lmax[k];
        for (int o = 16; o > 0; o >>= 1) v = fmaxf(v, __shfl_xor_sync(0xffffffffu, v, o));
        if (lane == 0) wbuf[k*8 + wid] = v;
    }
    __syncthreads();
    if (tid < 16) {
        float m = -FLT_MAX;
        for (int ww = 0; ww < 8; ww++) m = fmaxf(m, wbuf[tid*8 + ww]);
        maxs[tid] = m;
    }
    __syncthreads();

    // exp + local sum
    float lsum[16];
#pragma unroll
    for (int k = 0; k < 16; k++) lsum[k] = 0.f;
    for (int j = tid; j < JJJ; j += 256) {
        bool masked = (j > i + 16);
        if (masked) {
#pragma unroll
            for (int k = 0; k < 16; k++) sPre[k*JJJ + j] = 0.f;
        } else {
#pragma unroll
            for (int k = 0; k < 16; k++) {
                float e = __expf(sPre[k*JJJ + j] - maxs[k]);
                sPre[k*JJJ + j] = e;
                lsum[k] += e;
            }
        }
    }
#pragma unroll
    for (int k = 0; k < 16; k++) {
        float v = lsum[k];
        for (int o = 16; o > 0; o >>= 1) v += __shfl_xor_sync(0xffffffffu, v, o);
        if (lane == 0) wbuf[k*8 + wid] = v;
    }
    __syncthreads();
    if (tid < 16) {
        float s = 0.f;
        for (int ww = 0; ww < 8; ww++) s += wbuf[tid*8 + ww];
        sums[tid] = 1.0f / s;
    }
    __syncthreads();

    // normalize, write post, post-mix, write attn2
    for (int j = tid; j < JJJ; j += 256) {
        float a[16];
#pragma unroll
        for (int k = 0; k < 16; k++) {
            a[k] = sPre[k*JJJ + j] * sums[k];
            post[(((size_t)(b*16 + k))*NNN + i)*JJJ + j] = a[k];
        }
#pragma unroll
        for (int kk = 0; kk < 16; kk++) {
            float s = 0.f;
#pragma unroll
            for (int k = 0; k < 16; k++) s += a[k] * sQ[k*16 + kk];
            g_attn2[(((size_t)(b*16 + kk))*NNN + i)*JJJ + j] = s;
        }
    }
}

// ---------------- K4: out_heads = attn2 @ v  ----------------
// grid (32 m-tiles, 32 bh), block 128. N=64 (one tile), K=2064=43*48.
__global__ void k_av() {
    __shared__ float As[64*52];
    __shared__ float Bs[64*52];
    const int tid = threadIdx.x, lane = tid & 31, w = tid >> 5;
    const int mbase = blockIdx.x * 64;
    const int bh = blockIdx.y;
    const int b = bh >> 4, h = bh & 15;

    float acc[2][4][4];
#pragma unroll
    for (int a = 0; a < 2; a++)
#pragma unroll
        for (int bb = 0; bb < 4; bb++)
#pragma unroll
            for (int c = 0; c < 4; c++) acc[a][bb][c] = 0.f;

    const float* Abase = &g_attn2[((size_t)bh*NNN + mbase)*JJJ];
    const float* Bbase = &g_vT[(size_t)bh*DHH*JJJ];

    for (int kc = 0; kc < JJJ; kc += 48) {
#pragma unroll
        for (int t = 0; t < 6; t++) {
            int idx = tid + t*128;                // 768 float4
            int row = idx / 12, col4 = (idx % 12) * 4;
            float4 va = *(const float4*)&Abase[(size_t)row*JJJ + kc + col4];
            *(float4*)&As[row*52 + col4] = va;
            float4 vb = *(const float4*)&Bbase[(size_t)row*JJJ + kc + col4];
            *(float4*)&Bs[row*52 + col4] = vb;
        }
        __syncthreads();
        warp_tile_mma<52>(As, Bs, (w >> 1)*32, (w & 1)*32, 48, lane, acc);
        __syncthreads();
    }

    const int r = lane >> 2, q = lane & 3;
    const int mw = (w >> 1)*32, nw = (w & 1)*32;
#pragma unroll
    for (int mt = 0; mt < 2; mt++)
#pragma unroll
        for (int ci = 0; ci < 4; ci++) {
            int row = mbase + mw + mt*16 + r + ((ci & 2) ? 8 : 0);
#pragma unroll
            for (int nt = 0; nt < 4; nt++) {
                int d = nw + nt*8 + 2*q + (ci & 1);
                g_oh[((size_t)(b*NNN + row))*DIMM + h*DHH + d] = acc[mt][nt][ci];
            }
        }
}

// ---------------- K5: out = oh @ Wo^T + bo ----------------
// grid (16, 64), block 128
__global__ void k_outproj(const float* __restrict__ Wo, const float* __restrict__ bo,
                          float* __restrict__ out) {
    __shared__ float As[64*36];
    __shared__ float Bs[64*36];
    const int tid = threadIdx.x, lane = tid & 31, w = tid >> 5;
    const int mbase = blockIdx.y * 64;
    const int nbase = blockIdx.x * 64;

    float acc[2][4][4];
#pragma unroll
    for (int a = 0; a < 2; a++)
#pragma unroll
        for (int b = 0; b < 4; b++)
#pragma unroll
            for (int c = 0; c < 4; c++) acc[a][b][c] = 0.f;

    for (int kc = 0; kc < 1024; kc += 32) {
#pragma unroll
        for (int t = 0; t < 4; t++) {
            int idx = tid + t*128;
            int row = idx >> 3, col4 = (idx & 7) * 4;
            float4 va = *(const float4*)&g_oh[(size_t)(mbase + row)*1024 + kc + col4];
            *(float4*)&As[row*36 + col4] = va;
            float4 vb = *(const float4*)&Wo[(size_t)(nbase + row)*1024 + kc + col4];
            *(float4*)&Bs[row*36 + col4] = vb;
        }
        __syncthreads();
        warp_tile_mma<36>(As, Bs, (w >> 1)*32, (w & 1)*32, 32, lane, acc);
        __syncthreads();
    }

    const int r = lane >> 2, q = lane & 3;
    const int mw = (w >> 1)*32, nw = (w & 1)*32;
#pragma unroll
    for (int mt = 0; mt < 2; mt++)
#pragma unroll
        for (int ci = 0; ci < 4; ci++) {
            int row = mbase + mw + mt*16 + r + ((ci & 2) ? 8 : 0);
#pragma unroll
            for (int nt = 0; nt < 4; nt++) {
                int col = nbase + nw + nt*8 + 2*q + (ci & 1);
                out[(size_t)row*1024 + col] = acc[mt][nt][ci] + bo[col];
            }
        }
}

// ---------------- launch ----------------
extern "C" void kernel_launch(void* const* d_in, const int* in_sizes, int n_in,
                              void* d_out, int out_size) {
    const float* x     = (const float*)d_in[0];
    const float* rot   = (const float*)d_in[1];
    const float* Wq    = (const float*)d_in[2];
    const float* Wk    = (const float*)d_in[3];
    const float* Wv    = (const float*)d_in[4];
    const float* mem_k = (const float*)d_in[5];
    const float* mem_v = (const float*)d_in[6];
    const float* preP  = (const float*)d_in[7];
    const float* postP = (const float*)d_in[8];
    const float* Wo    = (const float*)d_in[9];
    const float* bo    = (const float*)d_in[10];

    float* out  = (float*)d_out;
    float* pre  = out + OFF_PRE;
    float* post = out + OFF_POST;

    const int smemD = (16*JJJ + 256 + 256 + 128 + 16 + 16) * sizeof(float);
    cudaFuncSetAttribute(k_mixsoftmax, cudaFuncAttributeMaxDynamicSharedMemorySize, smemD);

    k_memfill<<<BB*HHH, 256>>>(mem_k, mem_v);
    k_qkv<<<dim3(48, 64), 128>>>(x, Wq, Wk, Wv, rot);
    k_dots<<<dim3(33, 32, 32), 128>>>(pre);
    k_mixsoftmax<<<BB*NNN, 256, smemD>>>(pre, post, preP, postP);
    k_av<<<dim3(32, 32), 128>>>();
    k_outproj<<<dim3(16, 64), 128>>>(Wo, bo, out);
}

// round 2
// speedup vs baseline: 1.5096x; 1.5096x over previous
#include <cuda_runtime.h>
#include <cstdint>
#include <cfloat>
#include <math.h>

#define BB   2
#define NNN  2048
#define DIMM 1024
#define HHH  16
#define DHH  64
#define MMM  16
#define JJJ  2064   // M + N
#define ROTD 32

// d_out layout (floats): out | pre | post
#define OFF_OUT  0
#define OFF_PRE  (BB*NNN*DIMM)                       // 4194304
#define OFF_POST (OFF_PRE + BB*HHH*NNN*JJJ)         // 139460608

// ---- scratch (device globals; allocation-free rule) ----
__device__ float g_q  [BB*HHH*NNN*DHH];                 // (b,h,i,d)
__device__ float g_k  [BB*HHH*JJJ*DHH];                 // (b,h,j,d)  j=0..15 memory
__device__ float g_vT [BB*HHH*DHH*JJJ];                 // (b,h,d,j)
__device__ float g_attn2[(size_t)BB*HHH*NNN*JJJ];       // post-mixed attention
__device__ float g_oh [BB*NNN*HHH*DHH];                 // (b,i, h*64+d)

// ---------------- tf32 mma helpers ----------------
__device__ __forceinline__ uint32_t f2tf(float f) {
    uint32_t u; asm("cvt.rna.tf32.f32 %0, %1;" : "=r"(u) : "f"(f)); return u;
}
__device__ __forceinline__ void mma8(float c[4], const uint32_t a[4], const uint32_t b[2]) {
    asm volatile(
        "mma.sync.aligned.m16n8k8.row.col.f32.tf32.tf32.f32 "
        "{%0,%1,%2,%3},{%4,%5,%6,%7},{%8,%9},{%0,%1,%2,%3};"
        : "+f"(c[0]), "+f"(c[1]), "+f"(c[2]), "+f"(c[3])
        : "r"(a[0]), "r"(a[1]), "r"(a[2]), "r"(a[3]), "r"(b[0]), "r"(b[1]));
}

// Warp computes a 32x32 C tile from smem tiles As[64][S], Bs[64][S] (B stored as [n][k]).
template<int S>
__device__ __forceinline__ void warp_tile_mma(const float* As, const float* Bs,
                                              int mw, int nw, int kc, int lane,
                                              float acc[2][4][4]) {
    const int r = lane >> 2, q = lane & 3;
    for (int k0 = 0; k0 < kc; k0 += 8) {
        uint32_t a[2][4];
#pragma unroll
        for (int mt = 0; mt < 2; mt++) {
            const float* p = As + (mw + mt*16 + r) * S + k0 + q;
            a[mt][0] = f2tf(p[0]);
            a[mt][1] = f2tf(p[8*S]);
            a[mt][2] = f2tf(p[4]);
            a[mt][3] = f2tf(p[8*S + 4]);
        }
#pragma unroll
        for (int nt = 0; nt < 4; nt++) {
            const float* p = Bs + (nw + nt*8 + r) * S + k0 + q;
            uint32_t b[2];
            b[0] = f2tf(p[0]);
            b[1] = f2tf(p[4]);
#pragma unroll
            for (int mt = 0; mt < 2; mt++) mma8(acc[mt][nt], a[mt], b);
        }
    }
}

// ---------------- K0: broadcast memory K/V ----------------
__global__ void k_memfill(const float* __restrict__ mem_k, const float* __restrict__ mem_v) {
    int bh = blockIdx.x;            // b*16+h
    int h  = bh & 15;
    for (int idx = threadIdx.x; idx < MMM*DHH; idx += blockDim.x) {
        int j = idx >> 6, d = idx & 63;
        float kv = mem_k[(h*MMM + j)*DHH + d];
        float vv = mem_v[(h*MMM + j)*DHH + d];
        g_k [((size_t)bh*JJJ + j)*DHH + d] = kv;
        g_vT[((size_t)bh*DHH + d)*JJJ + j] = vv;
    }
}

// ---------------- K1: QKV projection + rotary ----------------
// grid (48, 64): x = n-tile (16 per matrix), y = m-tile. block 128.
__global__ void k_qkv(const float* __restrict__ x,
                      const float* __restrict__ Wq, const float* __restrict__ Wk,
                      const float* __restrict__ Wv, const float* __restrict__ rot) {
    __shared__ float As[64*36];
    __shared__ float Bs[64*36];
    const int tid = threadIdx.x, lane = tid & 31, w = tid >> 5;
    const int mbase = blockIdx.y * 64;
    const int ntile = blockIdx.x;
    const int which = ntile / 16;            // 0=q 1=k 2=v
    const float* W = (which == 0) ? Wq : (which == 1 ? Wk : Wv);
    const int nlocal = (ntile % 16) * 64;    // within the 1024-wide W
    const int h = ntile % 16;

    float acc[2][4][4];
#pragma unroll
    for (int a = 0; a < 2; a++)
#pragma unroll
        for (int b = 0; b < 4; b++)
#pragma unroll
            for (int c = 0; c < 4; c++) acc[a][b][c] = 0.f;

    for (int kc = 0; kc < 1024; kc += 32) {
#pragma unroll
        for (int t = 0; t < 4; t++) {
            int idx = tid + t*128;                 // float4 index, 512 total
            int row = idx >> 3, col4 = (idx & 7) * 4;
            float4 va = *(const float4*)&x[(size_t)(mbase + row)*1024 + kc + col4];
            *(float4*)&As[row*36 + col4] = va;
            float4 vb = *(const float4*)&W[(size_t)(nlocal + row)*1024 + kc + col4];
            *(float4*)&Bs[row*36 + col4] = vb;
        }
        __syncthreads();
        warp_tile_mma<36>(As, Bs, (w >> 1)*32, (w & 1)*32, 32, lane, acc);
        __syncthreads();
    }

    const int r = lane >> 2, q = lane & 3;
    const int mw = (w >> 1)*32, nw = (w & 1)*32;
    const bool lower = (nw == 0);

#pragma unroll
    for (int mt = 0; mt < 2; mt++) {
#pragma unroll
        for (int ci = 0; ci < 4; ci++) {
            int row = mbase + mw + mt*16 + r + ((ci & 2) ? 8 : 0);
            int b = row >> 11, i = row & 2047;
            if (which < 2 && lower) {
                // rotary: pair (d, d+16) lives in (nt, nt+2)
#pragma unroll
                for (int nt = 0; nt < 2; nt++) {
                    int d = nt*8 + 2*q + (ci & 1);          // 0..15
                    float lo = acc[mt][nt][ci];
                    float hi = acc[mt][nt + 2][ci];
                    float ang = rot[i*ROTD + d];            // rot repeats every 16
                    float cs = cosf(ang), sn = sinf(ang);
                    acc[mt][nt][ci]     = lo*cs - hi*sn;
                    acc[mt][nt + 2][ci] = hi*cs + lo*sn;
                }
            }
#pragma unroll
            for (int nt = 0; nt < 4; nt++) {
                int d = nw + nt*8 + 2*q + (ci & 1);
                float v = acc[mt][nt][ci];
                size_t bh = (size_t)(b*16 + h);
                if (which == 0)      g_q [(bh*NNN + i)*DHH + d] = v;
                else if (which == 1) g_k [(bh*JJJ + i + 16)*DHH + d] = v;
                else                 g_vT[(bh*DHH + d)*JJJ + (i + 16)] = v;
            }
        }
    }
}

// ---------------- K2: dots = scale * q @ k^T  -> pre ----------------
// grid (33, 32, 32): x=j-tile, y=i-tile, z=bh. block 128.
__global__ void k_dots(float* __restrict__ pre) {
    __shared__ float As[64*68];
    __shared__ float Bs[64*68];
    const int tid = threadIdx.x, lane = tid & 31, w = tid >> 5;
    const int bh = blockIdx.z;
    const int mbase = blockIdx.y * 64;
    const int jbase = blockIdx.x * 64;

    // load q tile (64x64) and k tile (64x64, guarded)
#pragma unroll
    for (int t = 0; t < 8; t++) {
        int idx = tid + t*128;                 // 1024 float4
        int row = idx >> 4, col4 = (idx & 15) * 4;
        float4 va = *(const float4*)&g_q[((size_t)bh*NNN + mbase + row)*DHH + col4];
        *(float4*)&As[row*68 + col4] = va;
        int j = jbase + row;
        float4 vb = (j < JJJ)
            ? *(const float4*)&g_k[((size_t)bh*JJJ + j)*DHH + col4]
            : make_float4(0.f, 0.f, 0.f, 0.f);
        *(float4*)&Bs[row*68 + col4] = vb;
    }
    __syncthreads();

    float acc[2][4][4];
#pragma unroll
    for (int a = 0; a < 2; a++)
#pragma unroll
        for (int b = 0; b < 4; b++)
#pragma unroll
            for (int c = 0; c < 4; c++) acc[a][b][c] = 0.f;

    warp_tile_mma<68>(As, Bs, (w >> 1)*32, (w & 1)*32, 64, lane, acc);

    const int r = lane >> 2, q = lane & 3;
    const int mw = (w >> 1)*32, nw = (w & 1)*32;
#pragma unroll
    for (int mt = 0; mt < 2; mt++)
#pragma unroll
        for (int ci = 0; ci < 4; ci++) {
            int row = mbase + mw + mt*16 + r + ((ci & 2) ? 8 : 0);
#pragma unroll
            for (int nt = 0; nt < 4; nt++) {
                int j = jbase + nw + nt*8 + 2*q + (ci & 1);
                if (j < JJJ)
                    pre[((size_t)bh*NNN + row)*JJJ + j] = acc[mt][nt][ci] * 0.125f;
            }
        }
}

// ---------------- K3: head-mix + mask + softmax + post-mix (warp-per-head) ----------------
// grid 4096 (b*2048+i), block 512 (16 warps; warp w owns output head k=w).
// Exploits causality: columns j > i+16 are exactly 0 in post/attn2 -> skip them.
__global__ void k_mixsoftmax(const float* __restrict__ pre,
                             float* __restrict__ post,
                             const float* __restrict__ preP,
                             const float* __restrict__ postP) {
    extern __shared__ float sm[];
    float* sPre = sm;                    // [16][2064]
    float* sInv = sm + 16*JJJ;           // 16

    const int bx = blockIdx.x;
    const int b = bx >> 11, i = bx & 2047;
    const int tid = threadIdx.x, lane = tid & 31, w = tid >> 5;

    const int nvalid = i + 17;           // valid columns: j in [0, i+16]
    const int nv4 = (nvalid + 3) >> 2;

    // load only the valid prefix of each head row (float4)
    for (int h = 0; h < 16; h++) {
        const float4* src = (const float4*)&pre[(((size_t)(b*16 + h))*NNN + i)*JJJ];
        float4* dst = (float4*)&sPre[h*JJJ];
        for (int idx = tid; idx < nv4; idx += 512) dst[idx] = src[idx];
    }

    // per-warp mix coefficients: column w of preP
    float pk[16];
#pragma unroll
    for (int h = 0; h < 16; h++) pk[h] = __ldg(&preP[h*16 + w]);

    __syncthreads();

    // ---- mix1 in place, chunked (512 cols/chunk), fused max ----
    float lmax = -FLT_MAX;
    for (int cb = 0; cb < nvalid; cb += 512) {
        float vals[16];
#pragma unroll
        for (int t = 0; t < 16; t++) {
            int j = cb + t*32 + lane;
            float s = 0.f;
            if (j < nvalid) {
#pragma unroll
                for (int h = 0; h < 16; h++) s += sPre[h*JJJ + j] * pk[h];
                lmax = fmaxf(lmax, s);
            }
            vals[t] = s;
        }
        __syncthreads();   // all reads of chunk done before overwriting it
#pragma unroll
        for (int t = 0; t < 16; t++) {
            int j = cb + t*32 + lane;
            if (j < nvalid) sPre[w*JJJ + j] = vals[t];
        }
        // next chunk reads different columns; no barrier needed here
    }
#pragma unroll
    for (int o = 16; o > 0; o >>= 1) lmax = fmaxf(lmax, __shfl_xor_sync(0xffffffffu, lmax, o));

    // ---- exp + sum (warp-local; warp w only touches row w) ----
    float lsum = 0.f;
    for (int j = lane; j < nvalid; j += 32) {
        float e = __expf(sPre[w*JJJ + j] - lmax);
        sPre[w*JJJ + j] = e;
        lsum += e;
    }
#pragma unroll
    for (int o = 16; o > 0; o >>= 1) lsum += __shfl_xor_sync(0xffffffffu, lsum, o);
    float inv = 1.0f / lsum;

    // ---- write post row w (zeros in masked tail) ----
    {
        float* prow = post + (((size_t)(b*16 + w))*NNN + i)*JJJ;
        for (int j = lane; j < JJJ; j += 32)
            prow[j] = (j < nvalid) ? sPre[w*JJJ + j] * inv : 0.f;
    }
    if (lane == 0) sInv[w] = inv;
    __syncthreads();

    // ---- mix2: attn2[w][j] = sum_k exp[k][j]*inv[k]*postP[k][w] ----
    float ck[16];
#pragma unroll
    for (int k = 0; k < 16; k++) ck[k] = sInv[k] * __ldg(&postP[k*16 + w]);

    float* arow = g_attn2 + (((size_t)(b*16 + w))*NNN + i)*JJJ;
    for (int j = lane; j < JJJ; j += 32) {
        float v = 0.f;
        if (j < nvalid) {
#pragma unroll
            for (int k = 0; k < 16; k++) v += sPre[k*JJJ + j] * ck[k];
        }
        arow[j] = v;
    }
}

// ---------------- K4: out_heads = attn2 @ v  ----------------
// grid (32 m-tiles, 32 bh), block 128. Causal: rows < mbase+64 only attend j <= mbase+79.
__global__ void k_av() {
    __shared__ float As[64*52];
    __shared__ float Bs[64*52];
    const int tid = threadIdx.x, lane = tid & 31, w = tid >> 5;
    const int mbase = blockIdx.x * 64;
    const int bh = blockIdx.y;
    const int b = bh >> 4, h = bh & 15;

    float acc[2][4][4];
#pragma unroll
    for (int a = 0; a < 2; a++)
#pragma unroll
        for (int bb = 0; bb < 4; bb++)
#pragma unroll
            for (int c = 0; c < 4; c++) acc[a][bb][c] = 0.f;

    const float* Abase = &g_attn2[((size_t)bh*NNN + mbase)*JJJ];
    const float* Bbase = &g_vT[(size_t)bh*DHH*JJJ];

    // only j <= (mbase+63)+16 can be nonzero; round up to the 48-chunk
    int kcend = mbase + 80;
    kcend = ((kcend + 47) / 48) * 48;
    if (kcend > JJJ) kcend = JJJ;

    for (int kc = 0; kc < kcend; kc += 48) {
#pragma unroll
        for (int t = 0; t < 6; t++) {
            int idx = tid + t*128;                // 768 float4
            int row = idx / 12, col4 = (idx % 12) * 4;
            float4 va = *(const float4*)&Abase[(size_t)row*JJJ + kc + col4];
            *(float4*)&As[row*52 + col4] = va;
            float4 vb = *(const float4*)&Bbase[(size_t)row*JJJ + kc + col4];
            *(float4*)&Bs[row*52 + col4] = vb;
        }
        __syncthreads();
        warp_tile_mma<52>(As, Bs, (w >> 1)*32, (w & 1)*32, 48, lane, acc);
        __syncthreads();
    }

    const int r = lane >> 2, q = lane & 3;
    const int mw = (w >> 1)*32, nw = (w & 1)*32;
#pragma unroll
    for (int mt = 0; mt < 2; mt++)
#pragma unroll
        for (int ci = 0; ci < 4; ci++) {
            int row = mbase + mw + mt*16 + r + ((ci & 2) ? 8 : 0);
#pragma unroll
            for (int nt = 0; nt < 4; nt++) {
                int d = nw + nt*8 + 2*q + (ci & 1);
                g_oh[((size_t)(b*NNN + row))*DIMM + h*DHH + d] = acc[mt][nt][ci];
            }
        }
}

// ---------------- K5: out = oh @ Wo^T + bo ----------------
// grid (16, 64), block 128
__global__ void k_outproj(const float* __restrict__ Wo, const float* __restrict__ bo,
                          float* __restrict__ out) {
    __shared__ float As[64*36];
    __shared__ float Bs[64*36];
    const int tid = threadIdx.x, lane = tid & 31, w = tid >> 5;
    const int mbase = blockIdx.y * 64;
    const int nbase = blockIdx.x * 64;

    float acc[2][4][4];
#pragma unroll
    for (int a = 0; a < 2; a++)
#pragma unroll
        for (int b = 0; b < 4; b++)
#pragma unroll
            for (int c = 0; c < 4; c++) acc[a][b][c] = 0.f;

    for (int kc = 0; kc < 1024; kc += 32) {
#pragma unroll
        for (int t = 0; t < 4; t++) {
            int idx = tid + t*128;
            int row = idx >> 3, col4 = (idx & 7) * 4;
            float4 va = *(const float4*)&g_oh[(size_t)(mbase + row)*1024 + kc + col4];
            *(float4*)&As[row*36 + col4] = va;
            float4 vb = *(const float4*)&Wo[(size_t)(nbase + row)*1024 + kc + col4];
            *(float4*)&Bs[row*36 + col4] = vb;
        }
        __syncthreads();
        warp_tile_mma<36>(As, Bs, (w >> 1)*32, (w & 1)*32, 32, lane, acc);
        __syncthreads();
    }

    const int r = lane >> 2, q = lane & 3;
    const int mw = (w >> 1)*32, nw = (w & 1)*32;
#pragma unroll
    for (int mt = 0; mt < 2; mt++)
#pragma unroll
        for (int ci = 0; ci < 4; ci++) {
            int row = mbase + mw + mt*16 + r + ((ci & 2) ? 8 : 0);
#pragma unroll
            for (int nt = 0; nt < 4; nt++) {
                int col = nbase + nw + nt*8 + 2*q + (ci & 1);
                out[(size_t)row*1024 + col] = acc[mt][nt][ci] + bo[col];
            }
        }
}

// ---------------- launch ----------------
extern "C" void kernel_launch(void* const* d_in, const int* in_sizes, int n_in,
                              void* d_out, int out_size) {
    const float* x     = (const float*)d_in[0];
    const float* rot   = (const float*)d_in[1];
    const float* Wq    = (const float*)d_in[2];
    const float* Wk    = (const float*)d_in[3];
    const float* Wv    = (const float*)d_in[4];
    const float* mem_k = (const float*)d_in[5];
    const float* mem_v = (const float*)d_in[6];
    const float* preP  = (const float*)d_in[7];
    const float* postP = (const float*)d_in[8];
    const float* Wo    = (const float*)d_in[9];
    const float* bo    = (const float*)d_in[10];

    float* out  = (float*)d_out;
    float* pre  = out + OFF_PRE;
    float* post = out + OFF_POST;

    const int smemD = (16*JJJ + 16) * sizeof(float);
    cudaFuncSetAttribute(k_mixsoftmax, cudaFuncAttributeMaxDynamicSharedMemorySize, smemD);

    k_memfill<<<BB*HHH, 256>>>(mem_k, mem_v);
    k_qkv<<<dim3(48, 64), 128>>>(x, Wq, Wk, Wv, rot);
    k_dots<<<dim3(33, 32, 32), 128>>>(pre);
    k_mixsoftmax<<<BB*NNN, 512, smemD>>>(pre, post, preP, postP);
    k_av<<<dim3(32, 32), 128>>>();
    k_outproj<<<dim3(16, 64), 128>>>(Wo, bo, out);
}

// round 3
// speedup vs baseline: 1.5578x; 1.0319x over previous
#include <cuda_runtime.h>
#include <cstdint>
#include <cfloat>
#include <math.h>

#define BB   2
#define NNN  2048
#define DIMM 1024
#define HHH  16
#define DHH  64
#define MMM  16
#define JJJ  2064   // M + N
#define J4   516    // JJJ/4
#define ROTD 32

// d_out layout (floats): out | pre | post
#define OFF_OUT  0
#define OFF_PRE  (BB*NNN*DIMM)                       // 4194304
#define OFF_POST (OFF_PRE + BB*HHH*NNN*JJJ)         // 139460608

// ---- scratch (device globals; allocation-free rule) ----
__device__ float g_q  [BB*HHH*NNN*DHH];                 // (b,h,i,d)
__device__ float g_k  [BB*HHH*JJJ*DHH];                 // (b,h,j,d)  j=0..15 memory
__device__ float g_vT [BB*HHH*DHH*JJJ];                 // (b,h,d,j)
__device__ float g_attn2[(size_t)BB*HHH*NNN*JJJ];       // post-mixed attention
__device__ float g_oh [BB*NNN*HHH*DHH];                 // (b,i, h*64+d)

// ---------------- tf32 mma helpers ----------------
__device__ __forceinline__ uint32_t f2tf(float f) {
    uint32_t u; asm("cvt.rna.tf32.f32 %0, %1;" : "=r"(u) : "f"(f)); return u;
}
__device__ __forceinline__ void mma8(float c[4], const uint32_t a[4], const uint32_t b[2]) {
    asm volatile(
        "mma.sync.aligned.m16n8k8.row.col.f32.tf32.tf32.f32 "
        "{%0,%1,%2,%3},{%4,%5,%6,%7},{%8,%9},{%0,%1,%2,%3};"
        : "+f"(c[0]), "+f"(c[1]), "+f"(c[2]), "+f"(c[3])
        : "r"(a[0]), "r"(a[1]), "r"(a[2]), "r"(a[3]), "r"(b[0]), "r"(b[1]));
}

// Warp computes a 32x32 C tile from smem tiles As[64][S], Bs[64][S] (B stored as [n][k]).
template<int S>
__device__ __forceinline__ void warp_tile_mma(const float* As, const float* Bs,
                                              int mw, int nw, int kc, int lane,
                                              float acc[2][4][4]) {
    const int r = lane >> 2, q = lane & 3;
    for (int k0 = 0; k0 < kc; k0 += 8) {
        uint32_t a[2][4];
#pragma unroll
        for (int mt = 0; mt < 2; mt++) {
            const float* p = As + (mw + mt*16 + r) * S + k0 + q;
            a[mt][0] = f2tf(p[0]);
            a[mt][1] = f2tf(p[8*S]);
            a[mt][2] = f2tf(p[4]);
            a[mt][3] = f2tf(p[8*S + 4]);
        }
#pragma unroll
        for (int nt = 0; nt < 4; nt++) {
            const float* p = Bs + (nw + nt*8 + r) * S + k0 + q;
            uint32_t b[2];
            b[0] = f2tf(p[0]);
            b[1] = f2tf(p[4]);
#pragma unroll
            for (int mt = 0; mt < 2; mt++) mma8(acc[mt][nt], a[mt], b);
        }
    }
}

// ---------------- K0: broadcast memory K/V ----------------
__global__ void k_memfill(const float* __restrict__ mem_k, const float* __restrict__ mem_v) {
    int bh = blockIdx.x;            // b*16+h
    int h  = bh & 15;
    for (int idx = threadIdx.x; idx < MMM*DHH; idx += blockDim.x) {
        int j = idx >> 6, d = idx & 63;
        float kv = mem_k[(h*MMM + j)*DHH + d];
        float vv = mem_v[(h*MMM + j)*DHH + d];
        g_k [((size_t)bh*JJJ + j)*DHH + d] = kv;
        g_vT[((size_t)bh*DHH + d)*JJJ + j] = vv;
    }
}

// ---------------- K1: QKV projection + rotary ----------------
__global__ void k_qkv(const float* __restrict__ x,
                      const float* __restrict__ Wq, const float* __restrict__ Wk,
                      const float* __restrict__ Wv, const float* __restrict__ rot) {
    __shared__ float As[64*36];
    __shared__ float Bs[64*36];
    const int tid = threadIdx.x, lane = tid & 31, w = tid >> 5;
    const int mbase = blockIdx.y * 64;
    const int ntile = blockIdx.x;
    const int which = ntile / 16;            // 0=q 1=k 2=v
    const float* W = (which == 0) ? Wq : (which == 1 ? Wk : Wv);
    const int nlocal = (ntile % 16) * 64;    // within the 1024-wide W
    const int h = ntile % 16;

    float acc[2][4][4];
#pragma unroll
    for (int a = 0; a < 2; a++)
#pragma unroll
        for (int b = 0; b < 4; b++)
#pragma unroll
            for (int c = 0; c < 4; c++) acc[a][b][c] = 0.f;

    for (int kc = 0; kc < 1024; kc += 32) {
#pragma unroll
        for (int t = 0; t < 4; t++) {
            int idx = tid + t*128;                 // float4 index, 512 total
            int row = idx >> 3, col4 = (idx & 7) * 4;
            float4 va = *(const float4*)&x[(size_t)(mbase + row)*1024 + kc + col4];
            *(float4*)&As[row*36 + col4] = va;
            float4 vb = *(const float4*)&W[(size_t)(nlocal + row)*1024 + kc + col4];
            *(float4*)&Bs[row*36 + col4] = vb;
        }
        __syncthreads();
        warp_tile_mma<36>(As, Bs, (w >> 1)*32, (w & 1)*32, 32, lane, acc);
        __syncthreads();
    }

    const int r = lane >> 2, q = lane & 3;
    const int mw = (w >> 1)*32, nw = (w & 1)*32;
    const bool lower = (nw == 0);

#pragma unroll
    for (int mt = 0; mt < 2; mt++) {
#pragma unroll
        for (int ci = 0; ci < 4; ci++) {
            int row = mbase + mw + mt*16 + r + ((ci & 2) ? 8 : 0);
            int b = row >> 11, i = row & 2047;
            if (which < 2 && lower) {
#pragma unroll
                for (int nt = 0; nt < 2; nt++) {
                    int d = nt*8 + 2*q + (ci & 1);          // 0..15
                    float lo = acc[mt][nt][ci];
                    float hi = acc[mt][nt + 2][ci];
                    float ang = rot[i*ROTD + d];
                    float cs = cosf(ang), sn = sinf(ang);
                    acc[mt][nt][ci]     = lo*cs - hi*sn;
                    acc[mt][nt + 2][ci] = hi*cs + lo*sn;
                }
            }
#pragma unroll
            for (int nt = 0; nt < 4; nt++) {
                int d = nw + nt*8 + 2*q + (ci & 1);
                float v = acc[mt][nt][ci];
                size_t bh = (size_t)(b*16 + h);
                if (which == 0)      g_q [(bh*NNN + i)*DHH + d] = v;
                else if (which == 1) g_k [(bh*JJJ + i + 16)*DHH + d] = v;
                else                 g_vT[(bh*DHH + d)*JJJ + (i + 16)] = v;
            }
        }
    }
}

// ---------------- K2: dots = scale * q @ k^T  -> pre ----------------
__global__ void k_dots(float* __restrict__ pre) {
    __shared__ float As[64*68];
    __shared__ float Bs[64*68];
    const int tid = threadIdx.x, lane = tid & 31, w = tid >> 5;
    const int bh = blockIdx.z;
    const int mbase = blockIdx.y * 64;
    const int jbase = blockIdx.x * 64;

#pragma unroll
    for (int t = 0; t < 8; t++) {
        int idx = tid + t*128;                 // 1024 float4
        int row = idx >> 4, col4 = (idx & 15) * 4;
        float4 va = *(const float4*)&g_q[((size_t)bh*NNN + mbase + row)*DHH + col4];
        *(float4*)&As[row*68 + col4] = va;
        int j = jbase + row;
        float4 vb = (j < JJJ)
            ? *(const float4*)&g_k[((size_t)bh*JJJ + j)*DHH + col4]
            : make_float4(0.f, 0.f, 0.f, 0.f);
        *(float4*)&Bs[row*68 + col4] = vb;
    }
    __syncthreads();

    float acc[2][4][4];
#pragma unroll
    for (int a = 0; a < 2; a++)
#pragma unroll
        for (int b = 0; b < 4; b++)
#pragma unroll
            for (int c = 0; c < 4; c++) acc[a][b][c] = 0.f;

    warp_tile_mma<68>(As, Bs, (w >> 1)*32, (w & 1)*32, 64, lane, acc);

    const int r = lane >> 2, q = lane & 3;
    const int mw = (w >> 1)*32, nw = (w & 1)*32;
#pragma unroll
    for (int mt = 0; mt < 2; mt++)
#pragma unroll
        for (int ci = 0; ci < 4; ci++) {
            int row = mbase + mw + mt*16 + r + ((ci & 2) ? 8 : 0);
#pragma unroll
            for (int nt = 0; nt < 4; nt++) {
                int j = jbase + nw + nt*8 + 2*q + (ci & 1);
                if (j < JJJ)
                    pre[((size_t)bh*NNN + row)*JJJ + j] = acc[mt][nt][ci] * 0.125f;
            }
        }
}

// ---------------- K3: head-mix + mask + softmax + post-mix ----------------
// grid 4096, block 512 = 4 groups x 4 warps; warp (g, sub) does heads 4sub..4sub+3
// over column-quarter g. float4 smem, named per-group barriers.
__global__ __launch_bounds__(512, 1)
void k_mixsoftmax(const float* __restrict__ pre,
                  float* __restrict__ post,
                  const float* __restrict__ preP,
                  const float* __restrict__ postP) {
    extern __shared__ float sm[];
    float4* sP4  = (float4*)sm;          // [16][516] float4
    float* sRedM = sm + 16*JJJ;          // [16][4]
    float* sRedS = sRedM + 64;           // [16][4]
    float* sInv  = sRedS + 64;           // [16]

    const int bx = blockIdx.x;
    const int b = bx >> 11, i = bx & 2047;
    const int tid = threadIdx.x, lane = tid & 31, w = tid >> 5;
    const int sub = w & 3, g = w >> 2;

    const int nvalid = i + 17;
    const int nv4 = (nvalid + 3) >> 2;
    const int qsz = (nv4 + 3) >> 2;
    const int f0 = g*qsz;
    const int f1 = min(nv4, f0 + qsz);
    const int iters = (qsz + 31) >> 5;

    // load valid prefix of pre (float4)
    for (int h = 0; h < 16; h++) {
        const float4* src = (const float4*)&pre[(((size_t)(b*16 + h))*NNN + i)*JJJ];
        float4* dst = sP4 + h*J4;
        for (int c = tid; c < nv4; c += 512) dst[c] = src[c];
    }

    // mix1 coeffs: out heads 4sub..4sub+3
    float pk[4][16];
#pragma unroll
    for (int a = 0; a < 4; a++)
#pragma unroll
        for (int h = 0; h < 16; h++) pk[a][h] = __ldg(&preP[h*16 + 4*sub + a]);

    __syncthreads();

    // ---- mix1 (in place, per-group chunked) + per-head max ----
    float lmax[4] = {-FLT_MAX, -FLT_MAX, -FLT_MAX, -FLT_MAX};
    for (int it = 0; it < iters; it++) {
        int c = f0 + it*32 + lane;
        bool act = c < f1;
        float4 m[4];
#pragma unroll
        for (int a = 0; a < 4; a++) m[a] = make_float4(0.f, 0.f, 0.f, 0.f);
        if (act) {
#pragma unroll
            for (int h = 0; h < 16; h++) {
                float4 d = sP4[h*J4 + c];
#pragma unroll
                for (int a = 0; a < 4; a++) {
                    m[a].x += d.x*pk[a][h]; m[a].y += d.y*pk[a][h];
                    m[a].z += d.z*pk[a][h]; m[a].w += d.w*pk[a][h];
                }
            }
            int j0 = 4*c;
#pragma unroll
            for (int a = 0; a < 4; a++) {
                float mx;
                if (j0 + 3 < nvalid) {
                    mx = fmaxf(fmaxf(m[a].x, m[a].y), fmaxf(m[a].z, m[a].w));
                } else {
                    mx = m[a].x;                       // j0 < nvalid always holds for c < nv4
                    if (j0 + 1 < nvalid) mx = fmaxf(mx, m[a].y);
                    if (j0 + 2 < nvalid) mx = fmaxf(mx, m[a].z);
                }
                lmax[a] = fmaxf(lmax[a], mx);
            }
        }
        asm volatile("bar.sync %0, 128;" :: "r"(g + 1));   // group: reads done
        if (act) {
#pragma unroll
            for (int a = 0; a < 4; a++) sP4[(4*sub + a)*J4 + c] = m[a];
        }
        asm volatile("bar.sync %0, 128;" :: "r"(g + 1));   // group: writes done
    }

    // combine max across groups
#pragma unroll
    for (int a = 0; a < 4; a++) {
        float v = lmax[a];
#pragma unroll
        for (int o = 16; o > 0; o >>= 1) v = fmaxf(v, __shfl_xor_sync(0xffffffffu, v, o));
        if (lane == 0) sRedM[(4*sub + a)*4 + g] = v;
    }
    __syncthreads();
    float gmax[4];
#pragma unroll
    for (int a = 0; a < 4; a++) {
        const float* p = &sRedM[(4*sub + a)*4];
        gmax[a] = fmaxf(fmaxf(p[0], p[1]), fmaxf(p[2], p[3]));
    }

    // ---- exp + sum (zero masked comps in boundary float4) ----
    float lsum[4] = {0.f, 0.f, 0.f, 0.f};
    for (int c = f0 + lane; c < f1; c += 32) {
        int j0 = 4*c;
        bool full = (j0 + 3 < nvalid);
#pragma unroll
        for (int a = 0; a < 4; a++) {
            float4 e = sP4[(4*sub + a)*J4 + c];
            e.x = __expf(e.x - gmax[a]);
            e.y = (full || j0 + 1 < nvalid) ? __expf(e.y - gmax[a]) : 0.f;
            e.z = (full || j0 + 2 < nvalid) ? __expf(e.z - gmax[a]) : 0.f;
            e.w = full ? __expf(e.w - gmax[a]) : 0.f;
            sP4[(4*sub + a)*J4 + c] = e;
            lsum[a] += e.x + e.y + e.z + e.w;
        }
    }
#pragma unroll
    for (int a = 0; a < 4; a++) {
        float v = lsum[a];
#pragma unroll
        for (int o = 16; o > 0; o >>= 1) v += __shfl_xor_sync(0xffffffffu, v, o);
        if (lane == 0) sRedS[(4*sub + a)*4 + g] = v;
    }
    __syncthreads();
    if (tid < 16) {
        const float* p = &sRedS[tid*4];
        sInv[tid] = 1.0f / (p[0] + p[1] + p[2] + p[3]);
    }
    __syncthreads();

    // ---- write post (normalized), float4 ----
    float inv[4];
#pragma unroll
    for (int a = 0; a < 4; a++) inv[a] = sInv[4*sub + a];
    for (int c = f0 + lane; c < f1; c += 32) {
#pragma unroll
        for (int a = 0; a < 4; a++) {
            float4 e = sP4[(4*sub + a)*J4 + c];
            float4 o = make_float4(e.x*inv[a], e.y*inv[a], e.z*inv[a], e.w*inv[a]);
            float4* prow = (float4*)&post[(((size_t)(b*16 + 4*sub + a))*NNN + i)*JJJ];
            prow[c] = o;
        }
    }

    // ---- mix2 -> attn2 (STG float4, no smem writeback) ----
    float ck[4][16];
#pragma unroll
    for (int a = 0; a < 4; a++)
#pragma unroll
        for (int k = 0; k < 16; k++) ck[a][k] = sInv[k] * __ldg(&postP[k*16 + 4*sub + a]);

    for (int c = f0 + lane; c < f1; c += 32) {
        float4 m[4];
#pragma unroll
        for (int a = 0; a < 4; a++) m[a] = make_float4(0.f, 0.f, 0.f, 0.f);
#pragma unroll
        for (int h = 0; h < 16; h++) {
            float4 d = sP4[h*J4 + c];
#pragma unroll
            for (int a = 0; a < 4; a++) {
                m[a].x += d.x*ck[a][h]; m[a].y += d.y*ck[a][h];
                m[a].z += d.z*ck[a][h]; m[a].w += d.w*ck[a][h];
            }
        }
#pragma unroll
        for (int a = 0; a < 4; a++) {
            float4* arow = (float4*)&g_attn2[(((size_t)(b*16 + 4*sub + a))*NNN + i)*JJJ];
            arow[c] = m[a];
        }
    }

    // ---- masked tails: post zeros to JJJ; attn2 zeros only to k_av's read bound ----
    const int tstart = nv4*4;
    int kcend = ((((i >> 6) << 6) + 80 + 47) / 48) * 48;
    if (kcend > JJJ) kcend = JJJ;
    for (int h = 0; h < 16; h++) {
        float* prow = post + (((size_t)(b*16 + h))*NNN + i)*JJJ;
        for (int j = tstart + tid; j < JJJ; j += 512) prow[j] = 0.f;
        float* arow = g_attn2 + (((size_t)(b*16 + h))*NNN + i)*JJJ;
        for (int j = tstart + tid; j < kcend; j += 512) arow[j] = 0.f;
    }
}

// ---------------- K4: out_heads = attn2 @ v ----------------
__global__ void k_av() {
    __shared__ float As[64*52];
    __shared__ float Bs[64*52];
    const int tid = threadIdx.x, lane = tid & 31, w = tid >> 5;
    const int mbase = blockIdx.x * 64;
    const int bh = blockIdx.y;
    const int b = bh >> 4, h = bh & 15;

    float acc[2][4][4];
#pragma unroll
    for (int a = 0; a < 2; a++)
#pragma unroll
        for (int bb = 0; bb < 4; bb++)
#pragma unroll
            for (int c = 0; c < 4; c++) acc[a][bb][c] = 0.f;

    const float* Abase = &g_attn2[((size_t)bh*NNN + mbase)*JJJ];
    const float* Bbase = &g_vT[(size_t)bh*DHH*JJJ];

    int kcend = mbase + 80;
    kcend = ((kcend + 47) / 48) * 48;
    if (kcend > JJJ) kcend = JJJ;

    for (int kc = 0; kc < kcend; kc += 48) {
#pragma unroll
        for (int t = 0; t < 6; t++) {
            int idx = tid + t*128;                // 768 float4
            int row = idx / 12, col4 = (idx % 12) * 4;
            float4 va = *(const float4*)&Abase[(size_t)row*JJJ + kc + col4];
            *(float4*)&As[row*52 + col4] = va;
            float4 vb = *(const float4*)&Bbase[(size_t)row*JJJ + kc + col4];
            *(float4*)&Bs[row*52 + col4] = vb;
        }
        __syncthreads();
        warp_tile_mma<52>(As, Bs, (w >> 1)*32, (w & 1)*32, 48, lane, acc);
        __syncthreads();
    }

    const int r = lane >> 2, q = lane & 3;
    const int mw = (w >> 1)*32, nw = (w & 1)*32;
#pragma unroll
    for (int mt = 0; mt < 2; mt++)
#pragma unroll
        for (int ci = 0; ci < 4; ci++) {
            int row = mbase + mw + mt*16 + r + ((ci & 2) ? 8 : 0);
#pragma unroll
            for (int nt = 0; nt < 4; nt++) {
                int d = nw + nt*8 + 2*q + (ci & 1);
                g_oh[((size_t)(b*NNN + row))*DIMM + h*DHH + d] = acc[mt][nt][ci];
            }
        }
}

// ---------------- K5: out = oh @ Wo^T + bo ----------------
__global__ void k_outproj(const float* __restrict__ Wo, const float* __restrict__ bo,
                          float* __restrict__ out) {
    __shared__ float As[64*36];
    __shared__ float Bs[64*36];
    const int tid = threadIdx.x, lane = tid & 31, w = tid >> 5;
    const int mbase = blockIdx.y * 64;
    const int nbase = blockIdx.x * 64;

    float acc[2][4][4];
#pragma unroll
    for (int a = 0; a < 2; a++)
#pragma unroll
        for (int b = 0; b < 4; b++)
#pragma unroll
            for (int c = 0; c < 4; c++) acc[a][b][c] = 0.f;

    for (int kc = 0; kc < 1024; kc += 32) {
#pragma unroll
        for (int t = 0; t < 4; t++) {
            int idx = tid + t*128;
            int row = idx >> 3, col4 = (idx & 7) * 4;
            float4 va = *(const float4*)&g_oh[(size_t)(mbase + row)*1024 + kc + col4];
            *(float4*)&As[row*36 + col4] = va;
            float4 vb = *(const float4*)&Wo[(size_t)(nbase + row)*1024 + kc + col4];
            *(float4*)&Bs[row*36 + col4] = vb;
        }
        __syncthreads();
        warp_tile_mma<36>(As, Bs, (w >> 1)*32, (w & 1)*32, 32, lane, acc);
        __syncthreads();
    }

    const int r = lane >> 2, q = lane & 3;
    const int mw = (w >> 1)*32, nw = (w & 1)*32;
#pragma unroll
    for (int mt = 0; mt < 2; mt++)
#pragma unroll
        for (int ci = 0; ci < 4; ci++) {
            int row = mbase + mw + mt*16 + r + ((ci & 2) ? 8 : 0);
#pragma unroll
            for (int nt = 0; nt < 4; nt++) {
                int col = nbase + nw + nt*8 + 2*q + (ci & 1);
                out[(size_t)row*1024 + col] = acc[mt][nt][ci] + bo[col];
            }
        }
}

// ---------------- launch ----------------
extern "C" void kernel_launch(void* const* d_in, const int* in_sizes, int n_in,
                              void* d_out, int out_size) {
    const float* x     = (const float*)d_in[0];
    const float* rot   = (const float*)d_in[1];
    const float* Wq    = (const float*)d_in[2];
    const float* Wk    = (const float*)d_in[3];
    const float* Wv    = (const float*)d_in[4];
    const float* mem_k = (const float*)d_in[5];
    const float* mem_v = (const float*)d_in[6];
    const float* preP  = (const float*)d_in[7];
    const float* postP = (const float*)d_in[8];
    const float* Wo    = (const float*)d_in[9];
    const float* bo    = (const float*)d_in[10];

    float* out  = (float*)d_out;
    float* pre  = out + OFF_PRE;
    float* post = out + OFF_POST;

    const int smemD = (16*JJJ + 64 + 64 + 16) * sizeof(float);
    cudaFuncSetAttribute(k_mixsoftmax, cudaFuncAttributeMaxDynamicSharedMemorySize, smemD);

    k_memfill<<<BB*HHH, 256>>>(mem_k, mem_v);
    k_qkv<<<dim3(48, 64), 128>>>(x, Wq, Wk, Wv, rot);
    k_dots<<<dim3(33, 32, 32), 128>>>(pre);
    k_mixsoftmax<<<BB*NNN, 512, smemD>>>(pre, post, preP, postP);
    k_av<<<dim3(32, 32), 128>>>();
    k_outproj<<<dim3(16, 64), 128>>>(Wo, bo, out);
}

// round 4
// speedup vs baseline: 1.8448x; 1.1843x over previous
#include <cuda_runtime.h>
#include <cstdint>
#include <cfloat>
#include <math.h>

#define BB   2
#define NNN  2048
#define DIMM 1024
#define HHH  16
#define DHH  64
#define MMM  16
#define JJJ  2064   // M + N
#define J4   516    // JJJ/4
#define ROTD 32

// d_out layout (floats): out | pre | post
#define OFF_OUT  0
#define OFF_PRE  (BB*NNN*DIMM)
#define OFF_POST (OFF_PRE + BB*HHH*NNN*JJJ)

// ---- scratch (device globals; allocation-free rule) ----
__device__ float g_q  [BB*HHH*NNN*DHH];                 // (b,h,i,d)
__device__ float g_k  [BB*HHH*JJJ*DHH];                 // (b,h,j,d)
__device__ float g_vT [BB*HHH*DHH*JJJ];                 // (b,h,d,j)
__device__ float g_attn2[(size_t)BB*HHH*NNN*JJJ];       // mixed logits, then post-mixed attn
__device__ float g_oh [BB*NNN*HHH*DHH];                 // (b,i, h*64+d)
__device__ float g_stat_m  [BB*HHH*NNN];
__device__ float g_stat_inv[BB*HHH*NNN];

// ---------------- tf32 mma helpers ----------------
__device__ __forceinline__ uint32_t f2tf(float f) {
    uint32_t u; asm("cvt.rna.tf32.f32 %0, %1;" : "=r"(u) : "f"(f)); return u;
}
__device__ __forceinline__ uint4 f2tf4(float4 v) {
    uint4 u; u.x = f2tf(v.x); u.y = f2tf(v.y); u.z = f2tf(v.z); u.w = f2tf(v.w); return u;
}
__device__ __forceinline__ void mma8(float c[4], const uint32_t a[4], const uint32_t b[2]) {
    asm volatile(
        "mma.sync.aligned.m16n8k8.row.col.f32.tf32.tf32.f32 "
        "{%0,%1,%2,%3},{%4,%5,%6,%7},{%8,%9},{%0,%1,%2,%3};"
        : "+f"(c[0]), "+f"(c[1]), "+f"(c[2]), "+f"(c[3])
        : "r"(a[0]), "r"(a[1]), "r"(a[2]), "r"(a[3]), "r"(b[0]), "r"(b[1]));
}

// Warp computes a 32x32 C tile; smem tiles hold PRE-CONVERTED tf32 bits.
template<int S>
__device__ __forceinline__ void warp_tile_mma_u(const uint32_t* As, const uint32_t* Bs,
                                                int mw, int nw, int kc, int lane,
                                                float acc[2][4][4]) {
    const int r = lane >> 2, q = lane & 3;
    for (int k0 = 0; k0 < kc; k0 += 8) {
        uint32_t a[2][4];
#pragma unroll
        for (int mt = 0; mt < 2; mt++) {
            const uint32_t* p = As + (mw + mt*16 + r) * S + k0 + q;
            a[mt][0] = p[0];
            a[mt][1] = p[8*S];
            a[mt][2] = p[4];
            a[mt][3] = p[8*S + 4];
        }
#pragma unroll
        for (int nt = 0; nt < 4; nt++) {
            const uint32_t* p = Bs + (nw + nt*8 + r) * S + k0 + q;
            uint32_t b[2];
            b[0] = p[0];
            b[1] = p[4];
#pragma unroll
            for (int mt = 0; mt < 2; mt++) mma8(acc[mt][nt], a[mt], b);
        }
    }
}

// ---------------- K0: broadcast memory K/V ----------------
__global__ void k_memfill(const float* __restrict__ mem_k, const float* __restrict__ mem_v) {
    int bh = blockIdx.x;
    int h  = bh & 15;
    for (int idx = threadIdx.x; idx < MMM*DHH; idx += blockDim.x) {
        int j = idx >> 6, d = idx & 63;
        g_k [((size_t)bh*JJJ + j)*DHH + d] = mem_k[(h*MMM + j)*DHH + d];
        g_vT[((size_t)bh*DHH + d)*JJJ + j] = mem_v[(h*MMM + j)*DHH + d];
    }
}

// ---------------- K1: QKV projection + rotary ----------------
__global__ void k_qkv(const float* __restrict__ x,
                      const float* __restrict__ Wq, const float* __restrict__ Wk,
                      const float* __restrict__ Wv, const float* __restrict__ rot) {
    __shared__ uint32_t As[64*36];
    __shared__ uint32_t Bs[64*36];
    const int tid = threadIdx.x, lane = tid & 31, w = tid >> 5;
    const int mbase = blockIdx.y * 64;
    const int ntile = blockIdx.x;
    const int which = ntile / 16;
    const float* W = (which == 0) ? Wq : (which == 1 ? Wk : Wv);
    const int nlocal = (ntile % 16) * 64;
    const int h = ntile % 16;

    float acc[2][4][4];
#pragma unroll
    for (int a = 0; a < 2; a++)
#pragma unroll
        for (int b = 0; b < 4; b++)
#pragma unroll
            for (int c = 0; c < 4; c++) acc[a][b][c] = 0.f;

    for (int kc = 0; kc < 1024; kc += 32) {
#pragma unroll
        for (int t = 0; t < 4; t++) {
            int idx = tid + t*128;
            int row = idx >> 3, col4 = (idx & 7) * 4;
            float4 va = *(const float4*)&x[(size_t)(mbase + row)*1024 + kc + col4];
            *(uint4*)&As[row*36 + col4] = f2tf4(va);
            float4 vb = *(const float4*)&W[(size_t)(nlocal + row)*1024 + kc + col4];
            *(uint4*)&Bs[row*36 + col4] = f2tf4(vb);
        }
        __syncthreads();
        warp_tile_mma_u<36>(As, Bs, (w >> 1)*32, (w & 1)*32, 32, lane, acc);
        __syncthreads();
    }

    const int r = lane >> 2, q = lane & 3;
    const int mw = (w >> 1)*32, nw = (w & 1)*32;
    const bool lower = (nw == 0);

#pragma unroll
    for (int mt = 0; mt < 2; mt++) {
#pragma unroll
        for (int ci = 0; ci < 4; ci++) {
            int row = mbase + mw + mt*16 + r + ((ci & 2) ? 8 : 0);
            int b = row >> 11, i = row & 2047;
            if (which < 2 && lower) {
#pragma unroll
                for (int nt = 0; nt < 2; nt++) {
                    int d = nt*8 + 2*q + (ci & 1);
                    float lo = acc[mt][nt][ci];
                    float hi = acc[mt][nt + 2][ci];
                    float ang = rot[i*ROTD + d];
                    float cs = cosf(ang), sn = sinf(ang);
                    acc[mt][nt][ci]     = lo*cs - hi*sn;
                    acc[mt][nt + 2][ci] = hi*cs + lo*sn;
                }
            }
#pragma unroll
            for (int nt = 0; nt < 4; nt++) {
                int d = nw + nt*8 + 2*q + (ci & 1);
                float v = acc[mt][nt][ci];
                size_t bh = (size_t)(b*16 + h);
                if (which == 0)      g_q [(bh*NNN + i)*DHH + d] = v;
                else if (which == 1) g_k [(bh*JJJ + i + 16)*DHH + d] = v;
                else                 g_vT[(bh*DHH + d)*JJJ + (i + 16)] = v;
            }
        }
    }
}

// ---------------- K2: dots = scale * q @ k^T -> pre ----------------
__global__ void k_dots(float* __restrict__ pre) {
    __shared__ uint32_t As[64*68];
    __shared__ uint32_t Bs[64*68];
    const int tid = threadIdx.x, lane = tid & 31, w = tid >> 5;
    const int bh = blockIdx.z;
    const int mbase = blockIdx.y * 64;
    const int jbase = blockIdx.x * 64;

#pragma unroll
    for (int t = 0; t < 8; t++) {
        int idx = tid + t*128;
        int row = idx >> 4, col4 = (idx & 15) * 4;
        float4 va = *(const float4*)&g_q[((size_t)bh*NNN + mbase + row)*DHH + col4];
        *(uint4*)&As[row*68 + col4] = f2tf4(va);
        int j = jbase + row;
        float4 vb = (j < JJJ)
            ? *(const float4*)&g_k[((size_t)bh*JJJ + j)*DHH + col4]
            : make_float4(0.f, 0.f, 0.f, 0.f);
        *(uint4*)&Bs[row*68 + col4] = f2tf4(vb);
    }
    __syncthreads();

    float acc[2][4][4];
#pragma unroll
    for (int a = 0; a < 2; a++)
#pragma unroll
        for (int b = 0; b < 4; b++)
#pragma unroll
            for (int c = 0; c < 4; c++) acc[a][b][c] = 0.f;

    warp_tile_mma_u<68>(As, Bs, (w >> 1)*32, (w & 1)*32, 64, lane, acc);

    const int r = lane >> 2, q = lane & 3;
    const int mw = (w >> 1)*32, nw = (w & 1)*32;
#pragma unroll
    for (int mt = 0; mt < 2; mt++)
#pragma unroll
        for (int ci = 0; ci < 4; ci++) {
            int row = mbase + mw + mt*16 + r + ((ci & 2) ? 8 : 0);
#pragma unroll
            for (int nt = 0; nt < 4; nt++) {
                int j = jbase + nw + nt*8 + 2*q + (ci & 1);
                if (j < JJJ)
                    pre[((size_t)bh*NNN + row)*JJJ + j] = acc[mt][nt][ci] * 0.125f;
            }
        }
}

// ---------------- M1: mix1 + online softmax stats ----------------
// grid 4096 (b*2048+i), block 512 = 16 warps, warp w = out-head w. smem 32KB -> 2 CTAs/SM.
__global__ __launch_bounds__(512, 2)
void k_mix1(const float* __restrict__ pre, const float* __restrict__ preP) {
    __shared__ float4 sC[16][128];
    const int bx = blockIdx.x;
    const int b = bx >> 11, i = bx & 2047;
    const int tid = threadIdx.x, lane = tid & 31, w = tid >> 5;
    const int nvalid = i + 17;
    const int nv4 = (nvalid + 3) >> 2;

    float pk[16];
#pragma unroll
    for (int h = 0; h < 16; h++) pk[h] = __ldg(&preP[h*16 + w]);

    const float4* src = (const float4*)&pre[(((size_t)(b*16 + w))*NNN + i)*JJJ];
    float4* dst = (float4*)&g_attn2[(((size_t)(b*16 + w))*NNN + i)*JJJ];

    float m = -FLT_MAX, s = 0.f;

    for (int base = 0; base < nv4; base += 128) {
        int c4 = min(128, nv4 - base);
        for (int c = lane; c < c4; c += 32) sC[w][c] = src[base + c];
        __syncthreads();
        for (int c = lane; c < c4; c += 32) {
            float4 mx = make_float4(0.f, 0.f, 0.f, 0.f);
#pragma unroll
            for (int h = 0; h < 16; h++) {
                float4 d = sC[h][c];
                mx.x += d.x*pk[h]; mx.y += d.y*pk[h];
                mx.z += d.z*pk[h]; mx.w += d.w*pk[h];
            }
            dst[base + c] = mx;
            int j0 = 4*(base + c);
            float v0 = mx.x;
            float v1 = (j0 + 1 < nvalid) ? mx.y : -FLT_MAX;
            float v2 = (j0 + 2 < nvalid) ? mx.z : -FLT_MAX;
            float v3 = (j0 + 3 < nvalid) ? mx.w : -FLT_MAX;
            float cm = fmaxf(fmaxf(v0, v1), fmaxf(v2, v3));
            float mn = fmaxf(m, cm);
            float add = __expf(v0 - mn) + __expf(v1 - mn) + __expf(v2 - mn) + __expf(v3 - mn);
            s = s*__expf(m - mn) + add;
            m = mn;
        }
        __syncthreads();
    }

#pragma unroll
    for (int o = 16; o > 0; o >>= 1) {
        float om = __shfl_xor_sync(0xffffffffu, m, o);
        float os = __shfl_xor_sync(0xffffffffu, s, o);
        float mn = fmaxf(m, om);
        s = s*__expf(m - mn) + os*__expf(om - mn);
        m = mn;
    }
    if (lane == 0) {
        g_stat_m  [(size_t)(b*16 + w)*NNN + i] = m;
        g_stat_inv[(size_t)(b*16 + w)*NNN + i] = 1.0f / s;
    }
}

// ---------------- M2: exp + post + mix2 -> attn2 ----------------
__global__ __launch_bounds__(512, 2)
void k_mix2(float* __restrict__ post, const float* __restrict__ postP) {
    __shared__ float4 sC[16][128];
    __shared__ float sInv[16];
    const int bx = blockIdx.x;
    const int b = bx >> 11, i = bx & 2047;
    const int tid = threadIdx.x, lane = tid & 31, w = tid >> 5;
    const int nvalid = i + 17;
    const int nv4 = (nvalid + 3) >> 2;

    const float mmax = g_stat_m  [(size_t)(b*16 + w)*NNN + i];
    const float inv  = g_stat_inv[(size_t)(b*16 + w)*NNN + i];
    if (lane == 0) sInv[w] = inv;
    __syncthreads();

    float ck[16];
#pragma unroll
    for (int k = 0; k < 16; k++) ck[k] = sInv[k] * __ldg(&postP[k*16 + w]);

    float4* mrow = (float4*)&g_attn2[(((size_t)(b*16 + w))*NNN + i)*JJJ];
    float4* prow = (float4*)&post[(((size_t)(b*16 + w))*NNN + i)*JJJ];

    for (int base = 0; base < nv4; base += 128) {
        int c4 = min(128, nv4 - base);
        for (int c = lane; c < c4; c += 32) sC[w][c] = mrow[base + c];
        __syncthreads();
        for (int c = lane; c < c4; c += 32) {
            float4 v = sC[w][c];
            int j0 = 4*(base + c);
            float4 e;
            e.x = __expf(v.x - mmax);
            e.y = (j0 + 1 < nvalid) ? __expf(v.y - mmax) : 0.f;
            e.z = (j0 + 2 < nvalid) ? __expf(v.z - mmax) : 0.f;
            e.w = (j0 + 3 < nvalid) ? __expf(v.w - mmax) : 0.f;
            sC[w][c] = e;
            prow[base + c] = make_float4(e.x*inv, e.y*inv, e.z*inv, e.w*inv);
        }
        __syncthreads();
        for (int c = lane; c < c4; c += 32) {
            float4 acc = make_float4(0.f, 0.f, 0.f, 0.f);
#pragma unroll
            for (int k = 0; k < 16; k++) {
                float4 d = sC[k][c];
                acc.x += d.x*ck[k]; acc.y += d.y*ck[k];
                acc.z += d.z*ck[k]; acc.w += d.w*ck[k];
            }
            mrow[base + c] = acc;
        }
        __syncthreads();
    }

    // tails: post zeros to JJJ; attn2 zeros to k_av's read bound
    const float4 z4 = make_float4(0.f, 0.f, 0.f, 0.f);
    int kcend = ((((i >> 6) << 6) + 80 + 47) / 48) * 48;
    if (kcend > JJJ) kcend = JJJ;
    const int kc4 = kcend >> 2;
    const int ptail = J4 - nv4;
    for (int idx = tid; idx < 16*ptail; idx += 512) {
        int h = idx / ptail, c = nv4 + idx % ptail;
        ((float4*)&post[(((size_t)(b*16 + h))*NNN + i)*JJJ])[c] = z4;
    }
    int atail = kc4 - nv4; if (atail < 0) atail = 0;
    for (int idx = tid; idx < 16*atail; idx += 512) {
        int h = idx / atail, c = nv4 + idx % atail;
        ((float4*)&g_attn2[(((size_t)(b*16 + h))*NNN + i)*JJJ])[c] = z4;
    }
}

// ---------------- K4: out_heads = attn2 @ v ----------------
__global__ void k_av() {
    __shared__ uint32_t As[64*52];
    __shared__ uint32_t Bs[64*52];
    const int tid = threadIdx.x, lane = tid & 31, w = tid >> 5;
    const int mbase = blockIdx.x * 64;
    const int bh = blockIdx.y;
    const int b = bh >> 4, h = bh & 15;

    float acc[2][4][4];
#pragma unroll
    for (int a = 0; a < 2; a++)
#pragma unroll
        for (int bb = 0; bb < 4; bb++)
#pragma unroll
            for (int c = 0; c < 4; c++) acc[a][bb][c] = 0.f;

    const float* Abase = &g_attn2[((size_t)bh*NNN + mbase)*JJJ];
    const float* Bbase = &g_vT[(size_t)bh*DHH*JJJ];

    int kcend = mbase + 80;
    kcend = ((kcend + 47) / 48) * 48;
    if (kcend > JJJ) kcend = JJJ;

    for (int kc = 0; kc < kcend; kc += 48) {
#pragma unroll
        for (int t = 0; t < 6; t++) {
            int idx = tid + t*128;
            int row = idx / 12, col4 = (idx % 12) * 4;
            float4 va = *(const float4*)&Abase[(size_t)row*JJJ + kc + col4];
            *(uint4*)&As[row*52 + col4] = f2tf4(va);
            float4 vb = *(const float4*)&Bbase[(size_t)row*JJJ + kc + col4];
            *(uint4*)&Bs[row*52 + col4] = f2tf4(vb);
        }
        __syncthreads();
        warp_tile_mma_u<52>(As, Bs, (w >> 1)*32, (w & 1)*32, 48, lane, acc);
        __syncthreads();
    }

    const int r = lane >> 2, q = lane & 3;
    const int mw = (w >> 1)*32, nw = (w & 1)*32;
#pragma unroll
    for (int mt = 0; mt < 2; mt++)
#pragma unroll
        for (int ci = 0; ci < 4; ci++) {
            int row = mbase + mw + mt*16 + r + ((ci & 2) ? 8 : 0);
#pragma unroll
            for (int nt = 0; nt < 4; nt++) {
                int d = nw + nt*8 + 2*q + (ci & 1);
                g_oh[((size_t)(b*NNN + row))*DIMM + h*DHH + d] = acc[mt][nt][ci];
            }
        }
}

// ---------------- K5: out = oh @ Wo^T + bo ----------------
__global__ void k_outproj(const float* __restrict__ Wo, const float* __restrict__ bo,
                          float* __restrict__ out) {
    __shared__ uint32_t As[64*36];
    __shared__ uint32_t Bs[64*36];
    const int tid = threadIdx.x, lane = tid & 31, w = tid >> 5;
    const int mbase = blockIdx.y * 64;
    const int nbase = blockIdx.x * 64;

    float acc[2][4][4];
#pragma unroll
    for (int a = 0; a < 2; a++)
#pragma unroll
        for (int b = 0; b < 4; b++)
#pragma unroll
            for (int c = 0; c < 4; c++) acc[a][b][c] = 0.f;

    for (int kc = 0; kc < 1024; kc += 32) {
#pragma unroll
        for (int t = 0; t < 4; t++) {
            int idx = tid + t*128;
            int row = idx >> 3, col4 = (idx & 7) * 4;
            float4 va = *(const float4*)&g_oh[(size_t)(mbase + row)*1024 + kc + col4];
            *(uint4*)&As[row*36 + col4] = f2tf4(va);
            float4 vb = *(const float4*)&Wo[(size_t)(nbase + row)*1024 + kc + col4];
            *(uint4*)&Bs[row*36 + col4] = f2tf4(vb);
        }
        __syncthreads();
        warp_tile_mma_u<36>(As, Bs, (w >> 1)*32, (w & 1)*32, 32, lane, acc);
        __syncthreads();
    }

    const int r = lane >> 2, q = lane & 3;
    const int mw = (w >> 1)*32, nw = (w & 1)*32;
#pragma unroll
    for (int mt = 0; mt < 2; mt++)
#pragma unroll
        for (int ci = 0; ci < 4; ci++) {
            int row = mbase + mw + mt*16 + r + ((ci & 2) ? 8 : 0);
#pragma unroll
            for (int nt = 0; nt < 4; nt++) {
                int col = nbase + nw + nt*8 + 2*q + (ci & 1);
                out[(size_t)row*1024 + col] = acc[mt][nt][ci] + bo[col];
            }
        }
}

// ---------------- launch ----------------
extern "C" void kernel_launch(void* const* d_in, const int* in_sizes, int n_in,
                              void* d_out, int out_size) {
    const float* x     = (const float*)d_in[0];
    const float* rot   = (const float*)d_in[1];
    const float* Wq    = (const float*)d_in[2];
    const float* Wk    = (const float*)d_in[3];
    const float* Wv    = (const float*)d_in[4];
    const float* mem_k = (const float*)d_in[5];
    const float* mem_v = (const float*)d_in[6];
    const float* preP  = (const float*)d_in[7];
    const float* postP = (const float*)d_in[8];
    const float* Wo    = (const float*)d_in[9];
    const float* bo    = (const float*)d_in[10];

    float* out  = (float*)d_out;
    float* pre  = out + OFF_PRE;
    float* post = out + OFF_POST;

    k_memfill<<<BB*HHH, 256>>>(mem_k, mem_v);
    k_qkv<<<dim3(48, 64), 128>>>(x, Wq, Wk, Wv, rot);
    k_dots<<<dim3(33, 32, 32), 128>>>(pre);
    k_mix1<<<BB*NNN, 512>>>(pre, preP);
    k_mix2<<<BB*NNN, 512>>>(post, postP);
    k_av<<<dim3(32, 32), 128>>>();
    k_outproj<<<dim3(16, 64), 128>>>(Wo, bo, out);
}